// round 1
// baseline (speedup 1.0000x reference)
#include <cuda_runtime.h>
#include <math.h>

#define BH 16
#define LSEQ 2048
#define DH 64
#define MT 64      // q rows per CTA
#define NT 64      // k cols per tile
#define STRD 68    // smem row stride (floats), 16B-aligned, conflict-friendly

#define OUT_ELE (LSEQ * DH * BH)          // 2048*1024
#define ATT_ELE ((size_t)BH * LSEQ * LSEQ)

__device__ float g_logZ[BH * LSEQ];

// -------------------- Kernel 1: S = QK^T/8, online logsumexp --------------------
__global__ __launch_bounds__(256) void sdpa_qk_pass1(const float* __restrict__ q,
                                                     const float* __restrict__ k,
                                                     float* __restrict__ Sout) {
    __shared__ float sQ[DH * STRD];  // [d][m]
    __shared__ float sK[DH * STRD];  // [d][n]
    const int tid = threadIdx.x;
    const int tx = tid & 15;
    const int ty = tid >> 4;
    const int b = blockIdx.y;
    const int qbase = blockIdx.x * MT;

    // Load Q tile (64x64), transposed into [d][m]
    const float* qp = q + ((size_t)b * LSEQ + qbase) * DH;
#pragma unroll
    for (int r = 0; r < 4; ++r) {
        int f = tid + 256 * r;     // 0..1023
        int row = f >> 4;
        int d4 = f & 15;
        float4 vv = *(const float4*)(qp + row * DH + d4 * 4);
        sQ[(d4 * 4 + 0) * STRD + row] = vv.x;
        sQ[(d4 * 4 + 1) * STRD + row] = vv.y;
        sQ[(d4 * 4 + 2) * STRD + row] = vv.z;
        sQ[(d4 * 4 + 3) * STRD + row] = vv.w;
    }

    float m_run[4], l_run[4];
#pragma unroll
    for (int i = 0; i < 4; ++i) { m_run[i] = -INFINITY; l_run[i] = 0.f; }

    for (int kt = 0; kt < LSEQ / NT; ++kt) {
        const float* kp = k + ((size_t)b * LSEQ + kt * NT) * DH;
        __syncthreads();
#pragma unroll
        for (int r = 0; r < 4; ++r) {
            int f = tid + 256 * r;
            int row = f >> 4;
            int d4 = f & 15;
            float4 vv = *(const float4*)(kp + row * DH + d4 * 4);
            sK[(d4 * 4 + 0) * STRD + row] = vv.x;
            sK[(d4 * 4 + 1) * STRD + row] = vv.y;
            sK[(d4 * 4 + 2) * STRD + row] = vv.z;
            sK[(d4 * 4 + 3) * STRD + row] = vv.w;
        }
        __syncthreads();

        float acc[4][4];
#pragma unroll
        for (int i = 0; i < 4; ++i)
#pragma unroll
            for (int j = 0; j < 4; ++j) acc[i][j] = 0.f;

#pragma unroll 8
        for (int d = 0; d < DH; ++d) {
            float4 a = *(const float4*)&sQ[d * STRD + 4 * ty];
            float4 bb = *(const float4*)&sK[d * STRD + 4 * tx];
            acc[0][0] += a.x * bb.x; acc[0][1] += a.x * bb.y; acc[0][2] += a.x * bb.z; acc[0][3] += a.x * bb.w;
            acc[1][0] += a.y * bb.x; acc[1][1] += a.y * bb.y; acc[1][2] += a.y * bb.z; acc[1][3] += a.y * bb.w;
            acc[2][0] += a.z * bb.x; acc[2][1] += a.z * bb.y; acc[2][2] += a.z * bb.z; acc[2][3] += a.z * bb.w;
            acc[3][0] += a.w * bb.x; acc[3][1] += a.w * bb.y; acc[3][2] += a.w * bb.z; acc[3][3] += a.w * bb.w;
        }

#pragma unroll
        for (int i = 0; i < 4; ++i) {
            float s0 = acc[i][0] * 0.125f;
            float s1 = acc[i][1] * 0.125f;
            float s2 = acc[i][2] * 0.125f;
            float s3 = acc[i][3] * 0.125f;

            // row max across 16 lanes (tx)
            float mx = fmaxf(fmaxf(s0, s1), fmaxf(s2, s3));
#pragma unroll
            for (int o = 8; o >= 1; o >>= 1)
                mx = fmaxf(mx, __shfl_xor_sync(0xffffffffu, mx, o));
            float mnew = fmaxf(m_run[i], mx);

            float se = __expf(s0 - mnew) + __expf(s1 - mnew) +
                       __expf(s2 - mnew) + __expf(s3 - mnew);
#pragma unroll
            for (int o = 8; o >= 1; o >>= 1)
                se += __shfl_xor_sync(0xffffffffu, se, o);

            l_run[i] = l_run[i] * __expf(m_run[i] - mnew) + se;
            m_run[i] = mnew;

            size_t off = ((size_t)b * LSEQ + qbase + 4 * ty + i) * LSEQ + kt * NT + 4 * tx;
            *(float4*)&Sout[off] = make_float4(s0, s1, s2, s3);
        }
    }

    if (tx == 0) {
#pragma unroll
        for (int i = 0; i < 4; ++i)
            g_logZ[b * LSEQ + qbase + 4 * ty + i] = m_run[i] + logf(l_run[i]);
    }
}

// -------- Kernel 2: attn = exp(S - logZ), log_attn = S - logZ, O = P V --------
__global__ __launch_bounds__(256) void sdpa_pv_pass2(const float* __restrict__ v,
                                                     float* __restrict__ attn,
                                                     float* __restrict__ log_attn,
                                                     float* __restrict__ outp) {
    __shared__ float sP[NT * STRD];  // [kk][m]
    __shared__ float sV[NT * STRD];  // [kk][d]
    const int tid = threadIdx.x;
    const int tx = tid & 15;
    const int ty = tid >> 4;
    const int b = blockIdx.y;
    const int qbase = blockIdx.x * MT;

    float lz[4];
#pragma unroll
    for (int i = 0; i < 4; ++i)
        lz[i] = g_logZ[b * LSEQ + qbase + 4 * ty + i];

    float acc[4][4];
#pragma unroll
    for (int i = 0; i < 4; ++i)
#pragma unroll
        for (int j = 0; j < 4; ++j) acc[i][j] = 0.f;

    for (int kt = 0; kt < LSEQ / NT; ++kt) {
        __syncthreads();
        // Load V tile [kk][d], row-major
        const float* vp = v + ((size_t)b * LSEQ + kt * NT) * DH;
#pragma unroll
        for (int r = 0; r < 4; ++r) {
            int f = tid + 256 * r;
            int row = f >> 4;
            int d4 = f & 15;
            float4 vv = *(const float4*)(vp + row * DH + d4 * 4);
            *(float4*)&sV[row * STRD + d4 * 4] = vv;
        }

        // Load S, compute P, write attn/log_attn, stage P^T into smem
#pragma unroll
        for (int i = 0; i < 4; ++i) {
            size_t off = ((size_t)b * LSEQ + qbase + 4 * ty + i) * LSEQ + kt * NT + 4 * tx;
            float4 s = *(const float4*)&attn[off];
            float la0 = s.x - lz[i];
            float la1 = s.y - lz[i];
            float la2 = s.z - lz[i];
            float la3 = s.w - lz[i];
            float p0 = __expf(la0);
            float p1 = __expf(la1);
            float p2 = __expf(la2);
            float p3 = __expf(la3);
            *(float4*)&attn[off] = make_float4(p0, p1, p2, p3);
            *(float4*)&log_attn[off] = make_float4(la0, la1, la2, la3);
            sP[(4 * tx + 0) * STRD + 4 * ty + i] = p0;
            sP[(4 * tx + 1) * STRD + 4 * ty + i] = p1;
            sP[(4 * tx + 2) * STRD + 4 * ty + i] = p2;
            sP[(4 * tx + 3) * STRD + 4 * ty + i] = p3;
        }
        __syncthreads();

#pragma unroll 8
        for (int kk = 0; kk < NT; ++kk) {
            float4 a = *(const float4*)&sP[kk * STRD + 4 * ty];
            float4 bv = *(const float4*)&sV[kk * STRD + 4 * tx];
            acc[0][0] += a.x * bv.x; acc[0][1] += a.x * bv.y; acc[0][2] += a.x * bv.z; acc[0][3] += a.x * bv.w;
            acc[1][0] += a.y * bv.x; acc[1][1] += a.y * bv.y; acc[1][2] += a.y * bv.z; acc[1][3] += a.y * bv.w;
            acc[2][0] += a.z * bv.x; acc[2][1] += a.z * bv.y; acc[2][2] += a.z * bv.z; acc[2][3] += a.z * bv.w;
            acc[3][0] += a.w * bv.x; acc[3][1] += a.w * bv.y; acc[3][2] += a.w * bv.z; acc[3][3] += a.w * bv.w;
        }
    }

    // output[l, b*64 + d] = O[b, l, d]
#pragma unroll
    for (int i = 0; i < 4; ++i) {
        size_t off = (size_t)(qbase + 4 * ty + i) * (DH * BH) + b * DH + 4 * tx;
        *(float4*)&outp[off] = make_float4(acc[i][0], acc[i][1], acc[i][2], acc[i][3]);
    }
}

extern "C" void kernel_launch(void* const* d_in, const int* in_sizes, int n_in,
                              void* d_out, int out_size) {
    const float* q = (const float*)d_in[0];
    const float* k = (const float*)d_in[1];
    const float* v = (const float*)d_in[2];

    float* outp = (float*)d_out;
    float* attn = outp + OUT_ELE;
    float* log_attn = attn + ATT_ELE;

    dim3 grid(LSEQ / MT, BH);
    sdpa_qk_pass1<<<grid, 256>>>(q, k, attn /* scratch for raw S */);
    sdpa_pv_pass2<<<grid, 256>>>(v, attn, log_attn, outp);
}

// round 3
// speedup vs baseline: 1.6099x; 1.6099x over previous
#include <cuda_runtime.h>
#include <cuda_bf16.h>
#include <cstdint>
#include <math.h>

#define BH 16
#define LSEQ 2048
#define DH 64
#define OUT_ELE (LSEQ * DH * BH)
#define ATT_ELE ((size_t)BH * LSEQ * LSEQ)

__device__ float g_logZ[BH * LSEQ];
__device__ __nv_bfloat16 g_Kh[BH * LSEQ * DH];
__device__ __nv_bfloat16 g_Kl[BH * LSEQ * DH];
__device__ __nv_bfloat16 g_Vth[BH * DH * LSEQ];
__device__ __nv_bfloat16 g_Vtl[BH * DH * LSEQ];

__device__ __forceinline__ uint32_t smem_u32(const void* p) {
    uint32_t a;
    asm("{ .reg .u64 t; cvta.to.shared.u64 t, %1; cvt.u32.u64 %0, t; }" : "=r"(a) : "l"(p));
    return a;
}
__device__ __forceinline__ void ldsm4(uint32_t* r, uint32_t addr) {
    asm volatile("ldmatrix.sync.aligned.m8n8.x4.shared.b16 {%0,%1,%2,%3}, [%4];"
                 : "=r"(r[0]), "=r"(r[1]), "=r"(r[2]), "=r"(r[3]) : "r"(addr));
}
__device__ __forceinline__ void mma16816(float* c, const uint32_t* a, uint32_t b0, uint32_t b1) {
    asm volatile("mma.sync.aligned.m16n8k16.row.col.f32.bf16.bf16.f32 "
                 "{%0,%1,%2,%3}, {%4,%5,%6,%7}, {%8,%9}, {%0,%1,%2,%3};"
                 : "+f"(c[0]), "+f"(c[1]), "+f"(c[2]), "+f"(c[3])
                 : "r"(a[0]), "r"(a[1]), "r"(a[2]), "r"(a[3]), "r"(b0), "r"(b1));
}
__device__ __forceinline__ void split2(float a, float b, uint32_t& hi, uint32_t& lo) {
    __nv_bfloat16 ah = __float2bfloat16(a), bh = __float2bfloat16(b);
    float al = a - __bfloat162float(ah);
    float bl = b - __bfloat162float(bh);
    __nv_bfloat162 H; H.x = ah; H.y = bh;
    __nv_bfloat162 L; L.x = __float2bfloat16(al); L.y = __float2bfloat16(bl);
    hi = *reinterpret_cast<uint32_t*>(&H);
    lo = *reinterpret_cast<uint32_t*>(&L);
}

// ---------------- Prepass: split K, transpose+split V ----------------
__global__ void prep_k(const float* __restrict__ k) {
    int idx = blockIdx.x * 256 + threadIdx.x;   // float4 index, total 524288
    float4 x = ((const float4*)k)[idx];
    uint32_t h0, l0, h1, l1;
    split2(x.x, x.y, h0, l0);
    split2(x.z, x.w, h1, l1);
    ((uint2*)g_Kh)[idx] = make_uint2(h0, h1);
    ((uint2*)g_Kl)[idx] = make_uint2(l0, l1);
}

__global__ void prep_v(const float* __restrict__ v) {
    __shared__ float vs[128 * 65];
    const int b = blockIdx.x >> 4, st = blockIdx.x & 15, tid = threadIdx.x;
    const float4* vp = (const float4*)(v + ((size_t)(b * LSEQ + st * 128)) * DH);
#pragma unroll
    for (int it = 0; it < 8; ++it) {
        int fi = it * 256 + tid;
        int s = fi >> 4, d4 = fi & 15;
        float4 x = vp[fi];
        vs[s * 65 + d4 * 4 + 0] = x.x;
        vs[s * 65 + d4 * 4 + 1] = x.y;
        vs[s * 65 + d4 * 4 + 2] = x.z;
        vs[s * 65 + d4 * 4 + 3] = x.w;
    }
    __syncthreads();
#pragma unroll
    for (int it = 0; it < 4; ++it) {
        int fo = it * 256 + tid;
        int d = fo >> 4, cu = fo & 15;
        float vv[8];
#pragma unroll
        for (int j = 0; j < 8; ++j) vv[j] = vs[(cu * 8 + j) * 65 + d];
        uint32_t hw[4], lw[4];
#pragma unroll
        for (int j = 0; j < 4; ++j) split2(vv[2 * j], vv[2 * j + 1], hw[j], lw[j]);
        size_t o = ((size_t)(b * DH + d)) * LSEQ + st * 128 + cu * 8;
        *(uint4*)(g_Vth + o) = make_uint4(hw[0], hw[1], hw[2], hw[3]);
        *(uint4*)(g_Vtl + o) = make_uint4(lw[0], lw[1], lw[2], lw[3]);
    }
}

// ---------------- Pass 1: S = (Q/8) K^T, logsumexp ----------------
// smem: QH 0 (16K), QL 16K, KH 32K, KL 48K, RED 64K (2KB) -> 67584 bytes
#define P1_SMEM 67584

__global__ void __launch_bounds__(256, 2)
sdpa_p1(const float* __restrict__ q, float* __restrict__ S) {
    extern __shared__ char sm[];
    const uint32_t sb = smem_u32(sm);
    const int tid = threadIdx.x, lane = tid & 31, wid = tid >> 5;
    const int wm = wid & 3, wn = wid >> 2;
    const int b = blockIdx.y, qbase = blockIdx.x * 128;

    // Q tile (128x64): scale 1/8, split, swizzled STS (128B rows, XOR-8)
    const float4* qp = (const float4*)(q + (size_t)(b * LSEQ + qbase) * DH);
#pragma unroll
    for (int r = 0; r < 8; ++r) {
        int fi = r * 256 + tid;
        int row = fi >> 4, d4 = fi & 15;
        float4 x = qp[fi];
        x.x *= 0.125f; x.y *= 0.125f; x.z *= 0.125f; x.w *= 0.125f;
        uint32_t h0, l0, h1, l1;
        split2(x.x, x.y, h0, l0);
        split2(x.z, x.w, h1, l1);
        uint32_t off = (uint32_t)row * 128 + ((((d4 >> 1) ^ (row & 7)) << 4) | ((d4 & 1) << 3));
        *(uint2*)(sm + off) = make_uint2(h0, h1);
        *(uint2*)(sm + 16384 + off) = make_uint2(l0, l1);
    }

    float m_run[4], l_run[4];
#pragma unroll
    for (int i = 0; i < 4; ++i) { m_run[i] = -INFINITY; l_run[i] = 0.f; }

    const int arow = lane & 15, achk0 = lane >> 4;
    const int brow_off = ((lane >> 4) << 3) + (lane & 7), bchk0 = (lane >> 3) & 1;

    for (int t = 0; t < 16; ++t) {
        __syncthreads();
        const uint4* kh = (const uint4*)(g_Kh + (size_t)(b * LSEQ + t * 128) * DH);
        const uint4* kl = (const uint4*)(g_Kl + (size_t)(b * LSEQ + t * 128) * DH);
#pragma unroll
        for (int r = 0; r < 4; ++r) {
            int fo = r * 256 + tid;
            int row = fo >> 3, cu = fo & 7;
            uint32_t off = (uint32_t)row * 128 + ((cu ^ (row & 7)) << 4);
            *(uint4*)(sm + 32768 + off) = kh[fo];
            *(uint4*)(sm + 49152 + off) = kl[fo];
        }
        __syncthreads();

        float c[2][8][4];
#pragma unroll
        for (int mt = 0; mt < 2; ++mt)
#pragma unroll
            for (int nt = 0; nt < 8; ++nt)
#pragma unroll
                for (int j = 0; j < 4; ++j) c[mt][nt][j] = 0.f;

#pragma unroll
        for (int sp = 0; sp < 3; ++sp) {
            uint32_t Ab = sb + (sp == 2 ? 16384u : 0u);
            uint32_t Bb = sb + (sp == 1 ? 49152u : 32768u);
#pragma unroll
            for (int ks = 0; ks < 4; ++ks) {
                uint32_t a[2][4];
#pragma unroll
                for (int mt = 0; mt < 2; ++mt) {
                    int row = wm * 32 + mt * 16 + arow;
                    ldsm4(a[mt], Ab + row * 128 + (((ks * 2 + achk0) ^ (row & 7)) << 4));
                }
#pragma unroll
                for (int p = 0; p < 4; ++p) {
                    uint32_t bb[4];
                    int row = wn * 64 + p * 16 + brow_off;
                    ldsm4(bb, Bb + row * 128 + (((ks * 2 + bchk0) ^ (row & 7)) << 4));
#pragma unroll
                    for (int mt = 0; mt < 2; ++mt) {
                        mma16816(c[mt][2 * p], a[mt], bb[0], bb[1]);
                        mma16816(c[mt][2 * p + 1], a[mt], bb[2], bb[3]);
                    }
                }
            }
        }

        // stats + raw S store
#pragma unroll
        for (int mt = 0; mt < 2; ++mt) {
#pragma unroll
            for (int h = 0; h < 2; ++h) {
                const int sl = mt * 2 + h;
                float mx = -INFINITY;
#pragma unroll
                for (int nt = 0; nt < 8; ++nt)
                    mx = fmaxf(mx, fmaxf(c[mt][nt][2 * h], c[mt][nt][2 * h + 1]));
                mx = fmaxf(mx, __shfl_xor_sync(0xffffffffu, mx, 1));
                mx = fmaxf(mx, __shfl_xor_sync(0xffffffffu, mx, 2));
                float mnew = fmaxf(m_run[sl], mx);
                float se = 0.f;
#pragma unroll
                for (int nt = 0; nt < 8; ++nt)
                    se += __expf(c[mt][nt][2 * h] - mnew) + __expf(c[mt][nt][2 * h + 1] - mnew);
                se += __shfl_xor_sync(0xffffffffu, se, 1);
                se += __shfl_xor_sync(0xffffffffu, se, 2);
                l_run[sl] = l_run[sl] * __expf(m_run[sl] - mnew) + se;
                m_run[sl] = mnew;
            }
            int r0 = qbase + wm * 32 + mt * 16 + (lane >> 2);
            float* sp0 = S + ((size_t)b * LSEQ + r0) * LSEQ + t * 128 + wn * 64 + (lane & 3) * 2;
#pragma unroll
            for (int nt = 0; nt < 8; ++nt) {
                *(float2*)(sp0 + nt * 8) = make_float2(c[mt][nt][0], c[mt][nt][1]);
                *(float2*)(sp0 + 8 * LSEQ + nt * 8) = make_float2(c[mt][nt][2], c[mt][nt][3]);
            }
        }
    }

    // combine the two column halves (wn) per row
    if ((lane & 3) == 0) {
#pragma unroll
        for (int mt = 0; mt < 2; ++mt)
#pragma unroll
            for (int h = 0; h < 2; ++h) {
                int row = wm * 32 + mt * 16 + h * 8 + (lane >> 2);
                *(float2*)(sm + 65536 + (row * 2 + wn) * 8) =
                    make_float2(m_run[mt * 2 + h], l_run[mt * 2 + h]);
            }
    }
    __syncthreads();
    if (tid < 128) {
        float2 a = *(float2*)(sm + 65536 + (tid * 2) * 8);
        float2 cc = *(float2*)(sm + 65536 + (tid * 2 + 1) * 8);
        float m = fmaxf(a.x, cc.x);
        float l = a.y * __expf(a.x - m) + cc.y * __expf(cc.x - m);
        g_logZ[b * LSEQ + qbase + tid] = m + logf(l);
    }
}

// ---------------- Pass 2: attn/log_attn + O = P V ----------------
// smem: PH 0 (32K), PL 32K, VH 64K (16K), VL 80K (16K), LZS 96K (512B) -> 98816
#define P2_SMEM 98816

__global__ void __launch_bounds__(256, 2)
sdpa_p2(float* attn, float* __restrict__ lattn, float* __restrict__ outp) {
    extern __shared__ char sm[];
    const uint32_t sb = smem_u32(sm);
    const int tid = threadIdx.x, lane = tid & 31, wid = tid >> 5;
    const int wm = wid & 3, wn = wid >> 2;
    const int b = blockIdx.y, qbase = blockIdx.x * 128;

    float* lzs = (float*)(sm + 98304);
    if (tid < 128) lzs[tid] = g_logZ[b * LSEQ + qbase + tid];

    float c[2][4][4];
#pragma unroll
    for (int mt = 0; mt < 2; ++mt)
#pragma unroll
        for (int nt = 0; nt < 4; ++nt)
#pragma unroll
            for (int j = 0; j < 4; ++j) c[mt][nt][j] = 0.f;

    const int arow = lane & 15, achk0 = lane >> 4;
    const int brow_off = ((lane >> 4) << 3) + (lane & 7), bchk0 = (lane >> 3) & 1;

    for (int t = 0; t < 16; ++t) {
        __syncthreads();
        // S -> attn/log_attn, P split into smem (256B rows, XOR-16)
#pragma unroll
        for (int it = 0; it < 16; ++it) {
            int fi = it * 256 + tid;
            int row = fi >> 5, c4 = fi & 31;
            size_t off = ((size_t)(b * LSEQ + qbase + row)) * LSEQ + t * 128 + c4 * 4;
            float4 s4 = *(float4*)(attn + off);
            float lz = lzs[row];
            float la0 = s4.x - lz, la1 = s4.y - lz, la2 = s4.z - lz, la3 = s4.w - lz;
            float p0 = __expf(la0), p1 = __expf(la1), p2 = __expf(la2), p3 = __expf(la3);
            *(float4*)(attn + off) = make_float4(p0, p1, p2, p3);
            *(float4*)(lattn + off) = make_float4(la0, la1, la2, la3);
            uint32_t h0, l0, h1, l1;
            split2(p0, p1, h0, l0);
            split2(p2, p3, h1, l1);
            uint32_t so = (uint32_t)row * 256 + ((((c4 >> 1) ^ (row & 15)) << 4) | ((c4 & 1) << 3));
            *(uint2*)(sm + so) = make_uint2(h0, h1);
            *(uint2*)(sm + 32768 + so) = make_uint2(l0, l1);
        }
        // V^T tile from prepass
#pragma unroll
        for (int it = 0; it < 4; ++it) {
            int fo = it * 256 + tid;
            int d = fo >> 4, cu = fo & 15;
            size_t o = ((size_t)(b * DH + d)) * LSEQ + t * 128 + cu * 8;
            uint32_t voff = (uint32_t)d * 256 + ((cu ^ (d & 15)) << 4);
            *(uint4*)(sm + 65536 + voff) = *(const uint4*)(g_Vth + o);
            *(uint4*)(sm + 81920 + voff) = *(const uint4*)(g_Vtl + o);
        }
        __syncthreads();

#pragma unroll
        for (int sp = 0; sp < 3; ++sp) {
            uint32_t Ab = sb + (sp == 2 ? 32768u : 0u);
            uint32_t Bb = sb + (sp == 1 ? 81920u : 65536u);
#pragma unroll
            for (int ks = 0; ks < 8; ++ks) {
                uint32_t a[2][4];
#pragma unroll
                for (int mt = 0; mt < 2; ++mt) {
                    int row = wm * 32 + mt * 16 + arow;
                    ldsm4(a[mt], Ab + row * 256 + (((ks * 2 + achk0) ^ (row & 15)) << 4));
                }
#pragma unroll
                for (int p = 0; p < 2; ++p) {
                    uint32_t bb[4];
                    int row = wn * 32 + p * 16 + brow_off;
                    ldsm4(bb, Bb + row * 256 + (((ks * 2 + bchk0) ^ (row & 15)) << 4));
#pragma unroll
                    for (int mt = 0; mt < 2; ++mt) {
                        mma16816(c[mt][2 * p], a[mt], bb[0], bb[1]);
                        mma16816(c[mt][2 * p + 1], a[mt], bb[2], bb[3]);
                    }
                }
            }
        }
    }

    // head-folded output
#pragma unroll
    for (int mt = 0; mt < 2; ++mt)
#pragma unroll
        for (int nt = 0; nt < 4; ++nt) {
            int r0 = qbase + wm * 32 + mt * 16 + (lane >> 2);
            int col = b * 64 + wn * 32 + nt * 8 + (lane & 3) * 2;
            float* dp = outp + (size_t)r0 * (DH * BH) + col;
            *(float2*)dp = make_float2(c[mt][nt][0], c[mt][nt][1]);
            *(float2*)(dp + 8 * (DH * BH)) = make_float2(c[mt][nt][2], c[mt][nt][3]);
        }
}

extern "C" void kernel_launch(void* const* d_in, const int* in_sizes, int n_in,
                              void* d_out, int out_size) {
    const float* q = (const float*)d_in[0];
    const float* k = (const float*)d_in[1];
    const float* v = (const float*)d_in[2];

    float* outp = (float*)d_out;
    float* attn = outp + OUT_ELE;
    float* lattn = attn + ATT_ELE;

    cudaFuncSetAttribute(sdpa_p1, cudaFuncAttributeMaxDynamicSharedMemorySize, P1_SMEM);
    cudaFuncSetAttribute(sdpa_p2, cudaFuncAttributeMaxDynamicSharedMemorySize, P2_SMEM);

    prep_k<<<2048, 256>>>(k);
    prep_v<<<256, 256>>>(v);

    dim3 grid(LSEQ / 128, BH);
    sdpa_p1<<<grid, 256, P1_SMEM>>>(q, attn /* raw S scratch */);
    sdpa_p2<<<grid, 256, P2_SMEM>>>(attn, lattn, outp);
}

// round 4
// speedup vs baseline: 2.2852x; 1.4194x over previous
#include <cuda_runtime.h>
#include <cuda_bf16.h>
#include <cstdint>
#include <math.h>

#define BH 16
#define LSEQ 2048
#define DH 64
#define OUT_ELE (LSEQ * DH * BH)
#define ATT_ELE ((size_t)BH * LSEQ * LSEQ)

__device__ __nv_bfloat16 g_Qh[BH * LSEQ * DH];
__device__ __nv_bfloat16 g_Ql[BH * LSEQ * DH];
__device__ __nv_bfloat16 g_Kh[BH * LSEQ * DH];
__device__ __nv_bfloat16 g_Kl[BH * LSEQ * DH];
__device__ __nv_bfloat16 g_Vth[BH * DH * LSEQ];
__device__ __nv_bfloat16 g_Vtl[BH * DH * LSEQ];

__device__ __forceinline__ uint32_t smem_u32(const void* p) {
    uint32_t a;
    asm("{ .reg .u64 t; cvta.to.shared.u64 t, %1; cvt.u32.u64 %0, t; }" : "=r"(a) : "l"(p));
    return a;
}
__device__ __forceinline__ void ldsm4(uint32_t* r, uint32_t addr) {
    asm volatile("ldmatrix.sync.aligned.m8n8.x4.shared.b16 {%0,%1,%2,%3}, [%4];"
                 : "=r"(r[0]), "=r"(r[1]), "=r"(r[2]), "=r"(r[3]) : "r"(addr));
}
__device__ __forceinline__ void mma16816(float* c, const uint32_t* a, uint32_t b0, uint32_t b1) {
    asm volatile("mma.sync.aligned.m16n8k16.row.col.f32.bf16.bf16.f32 "
                 "{%0,%1,%2,%3}, {%4,%5,%6,%7}, {%8,%9}, {%0,%1,%2,%3};"
                 : "+f"(c[0]), "+f"(c[1]), "+f"(c[2]), "+f"(c[3])
                 : "r"(a[0]), "r"(a[1]), "r"(a[2]), "r"(a[3]), "r"(b0), "r"(b1));
}
__device__ __forceinline__ void split2(float a, float b, uint32_t& hi, uint32_t& lo) {
    __nv_bfloat16 ah = __float2bfloat16(a), bh = __float2bfloat16(b);
    float al = a - __bfloat162float(ah);
    float bl = b - __bfloat162float(bh);
    __nv_bfloat162 H; H.x = ah; H.y = bh;
    __nv_bfloat162 L; L.x = __float2bfloat16(al); L.y = __float2bfloat16(bl);
    hi = *reinterpret_cast<uint32_t*>(&H);
    lo = *reinterpret_cast<uint32_t*>(&L);
}
__device__ __forceinline__ void cpasync16(uint32_t dst, const void* src) {
    asm volatile("cp.async.cg.shared.global [%0], [%1], 16;" :: "r"(dst), "l"(src));
}
#define CP_COMMIT() asm volatile("cp.async.commit_group;" ::: "memory")
#define CP_WAIT1()  asm volatile("cp.async.wait_group 1;" ::: "memory")
#define CP_WAIT0()  asm volatile("cp.async.wait_group 0;" ::: "memory")
// pack high16 of two fp32 -> bf16x2 (truncation split, hi part)
__device__ __forceinline__ uint32_t prmt_hi(uint32_t a, uint32_t b) {
    uint32_t d;
    asm("prmt.b32 %0, %1, %2, 0x7632;" : "=r"(d) : "r"(a), "r"(b));
    return d;
}
__device__ __forceinline__ uint32_t cvt_bf16x2(float hi, float lo) {
    uint32_t d;
    asm("cvt.rn.bf16x2.f32 %0, %1, %2;" : "=r"(d) : "f"(hi), "f"(lo));
    return d;
}

// ---------------- Prepass ----------------
__global__ void prep_q(const float* __restrict__ q) {
    int idx = blockIdx.x * 256 + threadIdx.x;   // float4 index, 524288 total
    float4 x = ((const float4*)q)[idx];
    x.x *= 0.125f; x.y *= 0.125f; x.z *= 0.125f; x.w *= 0.125f;
    uint32_t h0, l0, h1, l1;
    split2(x.x, x.y, h0, l0);
    split2(x.z, x.w, h1, l1);
    ((uint2*)g_Qh)[idx] = make_uint2(h0, h1);
    ((uint2*)g_Ql)[idx] = make_uint2(l0, l1);
}
__global__ void prep_k(const float* __restrict__ k) {
    int idx = blockIdx.x * 256 + threadIdx.x;
    float4 x = ((const float4*)k)[idx];
    uint32_t h0, l0, h1, l1;
    split2(x.x, x.y, h0, l0);
    split2(x.z, x.w, h1, l1);
    ((uint2*)g_Kh)[idx] = make_uint2(h0, h1);
    ((uint2*)g_Kl)[idx] = make_uint2(l0, l1);
}
__global__ void prep_v(const float* __restrict__ v) {
    __shared__ float vs[128 * 65];
    const int b = blockIdx.x >> 4, st = blockIdx.x & 15, tid = threadIdx.x;
    const float4* vp = (const float4*)(v + ((size_t)(b * LSEQ + st * 128)) * DH);
#pragma unroll
    for (int it = 0; it < 8; ++it) {
        int fi = it * 256 + tid;
        int s = fi >> 4, d4 = fi & 15;
        float4 x = vp[fi];
        vs[s * 65 + d4 * 4 + 0] = x.x;
        vs[s * 65 + d4 * 4 + 1] = x.y;
        vs[s * 65 + d4 * 4 + 2] = x.z;
        vs[s * 65 + d4 * 4 + 3] = x.w;
    }
    __syncthreads();
#pragma unroll
    for (int it = 0; it < 4; ++it) {
        int fo = it * 256 + tid;
        int d = fo >> 4, cu = fo & 15;
        float vv[8];
#pragma unroll
        for (int j = 0; j < 8; ++j) vv[j] = vs[(cu * 8 + j) * 65 + d];
        uint32_t hw[4], lw[4];
#pragma unroll
        for (int j = 0; j < 4; ++j) split2(vv[2 * j], vv[2 * j + 1], hw[j], lw[j]);
        size_t o = ((size_t)(b * DH + d)) * LSEQ + st * 128 + cu * 8;
        *(uint4*)(g_Vth + o) = make_uint4(hw[0], hw[1], hw[2], hw[3]);
        *(uint4*)(g_Vtl + o) = make_uint4(lw[0], lw[1], lw[2], lw[3]);
    }
}

// ---------------- Fused attention ----------------
// smem: QH 0, QL 16K | K buffers B0 32K, B1 64K | V buffers B2 96K, B3 128K
//       (each 32K = hi 16K + lo 16K) | lzs 160K (512B)
#define SQH 0
#define SQL 16384
#define SB0 32768
#define SB1 65536
#define SB2 98304
#define SB3 131072
#define SLZ 163840
#define SMEM_TOT 164352

__global__ void __launch_bounds__(256)
sdpa_fused(float* __restrict__ attn, float* __restrict__ lattn, float* __restrict__ outp) {
    extern __shared__ char sm[];
    const uint32_t sb = smem_u32(sm);
    const int tid = threadIdx.x, lane = tid & 31, w = tid >> 5;
    const int b = blockIdx.y, qbase = blockIdx.x * 128;

    const int arow = lane & 15, achk = lane >> 4;
    const int brow = ((lane >> 4) << 3) + (lane & 7), bch = (lane >> 3) & 1;

    // -------- async tile loaders (all 256 threads) --------
    const char* kh_base = (const char*)(g_Kh + (size_t)b * LSEQ * DH);
    const char* kl_base = (const char*)(g_Kl + (size_t)b * LSEQ * DH);
    const char* vh_base = (const char*)(g_Vth + (size_t)b * DH * LSEQ);
    const char* vl_base = (const char*)(g_Vtl + (size_t)b * DH * LSEQ);

#define LOAD_K(buf, t) do {                                                    \
        const char* _sh = kh_base + (size_t)(t) * 16384;                       \
        const char* _sl = kl_base + (size_t)(t) * 16384;                       \
        _Pragma("unroll")                                                      \
        for (int r = 0; r < 4; ++r) {                                          \
            int fo = r * 256 + tid;                                            \
            int row = fo >> 3, cu = fo & 7;                                    \
            uint32_t off = (uint32_t)row * 128 + ((cu ^ (row & 7)) << 4);      \
            cpasync16(sb + (buf) + off, _sh + fo * 16);                        \
            cpasync16(sb + (buf) + 16384 + off, _sl + fo * 16);                \
        }                                                                      \
    } while (0)

#define LOAD_V(buf, t) do {                                                    \
        const char* _sh = vh_base + (size_t)(t) * 256;                         \
        const char* _sl = vl_base + (size_t)(t) * 256;                         \
        _Pragma("unroll")                                                      \
        for (int r = 0; r < 4; ++r) {                                          \
            int fo = r * 256 + tid;                                            \
            int row = fo >> 4, cu = fo & 15;                                   \
            uint32_t off = (uint32_t)row * 256 + ((cu ^ (row & 15)) << 4);     \
            size_t sof = (size_t)row * (LSEQ * 2) + cu * 16;                   \
            cpasync16(sb + (buf) + off, _sh + sof);                            \
            cpasync16(sb + (buf) + 16384 + off, _sl + sof);                    \
        }                                                                      \
    } while (0)

    // prologue: Q tile + K tile 0 (one group)
    {
        const char* qh = (const char*)(g_Qh + (size_t)(b * LSEQ + qbase) * DH);
        const char* ql = (const char*)(g_Ql + (size_t)(b * LSEQ + qbase) * DH);
#pragma unroll
        for (int r = 0; r < 4; ++r) {
            int fo = r * 256 + tid;
            int row = fo >> 3, cu = fo & 7;
            uint32_t off = (uint32_t)row * 128 + ((cu ^ (row & 7)) << 4);
            cpasync16(sb + SQH + off, qh + fo * 16);
            cpasync16(sb + SQL + off, ql + fo * 16);
        }
        LOAD_K(SB0, 0);
        CP_COMMIT();
    }

    uint32_t aQh[4][4], aQl[4][4];
    float mrun[2] = {-INFINITY, -INFINITY}, lrun[2] = {0.f, 0.f};

    // QK compute into c[16][4] from K buffer at byte offset kb (hi), kb+16K (lo)
#define COMPUTE_QK(c, kb) do {                                                 \
        _Pragma("unroll")                                                      \
        for (int nt = 0; nt < 16; ++nt) {                                      \
            c[nt][0] = 0.f; c[nt][1] = 0.f; c[nt][2] = 0.f; c[nt][3] = 0.f;    \
        }                                                                      \
        _Pragma("unroll")                                                      \
        for (int ks = 0; ks < 4; ++ks) {                                       \
            _Pragma("unroll")                                                  \
            for (int p = 0; p < 8; ++p) {                                      \
                int row = p * 16 + brow;                                       \
                uint32_t ad = sb + (kb) + row * 128 +                          \
                              (((ks * 2 + bch) ^ (row & 7)) << 4);             \
                uint32_t bh_[4], bl_[4];                                       \
                ldsm4(bh_, ad);                                                \
                ldsm4(bl_, ad + 16384);                                        \
                mma16816(c[2 * p],     aQh[ks], bh_[0], bh_[1]);               \
                mma16816(c[2 * p + 1], aQh[ks], bh_[2], bh_[3]);               \
                mma16816(c[2 * p],     aQh[ks], bl_[0], bl_[1]);               \
                mma16816(c[2 * p + 1], aQh[ks], bl_[2], bl_[3]);               \
                mma16816(c[2 * p],     aQl[ks], bh_[0], bh_[1]);               \
                mma16816(c[2 * p + 1], aQl[ks], bh_[2], bh_[3]);               \
            }                                                                  \
        }                                                                      \
    } while (0)

    // ================= Sweep 1: stats =================
    for (int t = 0; t < 16; ++t) {
        if (t < 15) {
            LOAD_K((((t + 1) & 1) ? SB1 : SB0), t + 1);
            CP_COMMIT();
            CP_WAIT1();
        } else {
            CP_WAIT0();
        }
        __syncthreads();
        if (t == 0) {
#pragma unroll
            for (int ks = 0; ks < 4; ++ks) {
                int row = w * 16 + arow;
                uint32_t ad = sb + row * 128 + (((ks * 2 + achk) ^ (row & 7)) << 4);
                ldsm4(aQh[ks], ad);
                ldsm4(aQl[ks], ad + 16384);
            }
        }
        float c[16][4];
        COMPUTE_QK(c, ((t & 1) ? SB1 : SB0));
#pragma unroll
        for (int h = 0; h < 2; ++h) {
            float mx = mrun[h];
#pragma unroll
            for (int nt = 0; nt < 16; ++nt)
                mx = fmaxf(mx, fmaxf(c[nt][2 * h], c[nt][2 * h + 1]));
            float sum = 0.f;
#pragma unroll
            for (int nt = 0; nt < 16; ++nt)
                sum += __expf(c[nt][2 * h] - mx) + __expf(c[nt][2 * h + 1] - mx);
            lrun[h] = lrun[h] * __expf(mrun[h] - mx) + sum;
            mrun[h] = mx;
        }
        __syncthreads();
    }

    // combine across the 4 lanes sharing a row; write logZ to smem
    float* lzs = (float*)(sm + SLZ);
#pragma unroll
    for (int h = 0; h < 2; ++h) {
        float m = mrun[h], l = lrun[h];
#pragma unroll
        for (int o = 1; o <= 2; o <<= 1) {
            float om = __shfl_xor_sync(0xffffffffu, m, o);
            float ol = __shfl_xor_sync(0xffffffffu, l, o);
            float nm = fmaxf(m, om);
            l = l * __expf(m - nm) + ol * __expf(om - nm);
            m = nm;
        }
        if ((lane & 3) == 0) lzs[w * 16 + (lane >> 2) + 8 * h] = m + logf(l);
    }
    __syncthreads();
    const float lz0 = lzs[w * 16 + (lane >> 2)];
    const float lz1 = lzs[w * 16 + (lane >> 2) + 8];

    // ================= Sweep 2: emit + PV =================
    float o[8][4];
#pragma unroll
    for (int g = 0; g < 8; ++g)
#pragma unroll
        for (int j = 0; j < 4; ++j) o[g][j] = 0.f;

    LOAD_K(SB0, 0);
    LOAD_V(SB2, 0);
    CP_COMMIT();

    float* aRow = attn + ((size_t)(b * LSEQ + qbase + w * 16 + (lane >> 2))) * LSEQ + (lane & 3) * 2;
    float* lRow = lattn + ((size_t)(b * LSEQ + qbase + w * 16 + (lane >> 2))) * LSEQ + (lane & 3) * 2;

    for (int t = 0; t < 16; ++t) {
        if (t < 15) {
            LOAD_K((((t + 1) & 1) ? SB1 : SB0), t + 1);
            LOAD_V((((t + 1) & 1) ? SB3 : SB2), t + 1);
            CP_COMMIT();
            CP_WAIT1();
        } else {
            CP_WAIT0();
        }
        __syncthreads();

        float c[16][4];
        COMPUTE_QK(c, ((t & 1) ? SB1 : SB0));

        // convert S -> attn/lattn stores + register-resident P fragments
        uint32_t aPh[8][4], aPl[8][4];
        float* aT = aRow + t * 128;
        float* lT = lRow + t * 128;
#pragma unroll
        for (int kc = 0; kc < 8; ++kc) {
#pragma unroll
            for (int qq = 0; qq < 2; ++qq) {
                const int nt = 2 * kc + qq;
                float la0 = c[nt][0] - lz0, la1 = c[nt][1] - lz0;
                float la2 = c[nt][2] - lz1, la3 = c[nt][3] - lz1;
                float p0 = __expf(la0), p1 = __expf(la1);
                float p2 = __expf(la2), p3 = __expf(la3);
                *(float2*)(aT + nt * 8) = make_float2(p0, p1);
                *(float2*)(aT + 8 * LSEQ + nt * 8) = make_float2(p2, p3);
                *(float2*)(lT + nt * 8) = make_float2(la0, la1);
                *(float2*)(lT + 8 * LSEQ + nt * 8) = make_float2(la2, la3);
                uint32_t u0 = __float_as_uint(p0), u1 = __float_as_uint(p1);
                uint32_t u2 = __float_as_uint(p2), u3 = __float_as_uint(p3);
                aPh[kc][qq * 2 + 0] = prmt_hi(u0, u1);
                aPh[kc][qq * 2 + 1] = prmt_hi(u2, u3);
                aPl[kc][qq * 2 + 0] = cvt_bf16x2(p1 - __uint_as_float(u1 & 0xFFFF0000u),
                                                 p0 - __uint_as_float(u0 & 0xFFFF0000u));
                aPl[kc][qq * 2 + 1] = cvt_bf16x2(p3 - __uint_as_float(u3 & 0xFFFF0000u),
                                                 p2 - __uint_as_float(u2 & 0xFFFF0000u));
            }
        }

        // PV: O += Ph*Vh + Ph*Vl + Pl*Vh
        const uint32_t vb = sb + ((t & 1) ? SB3 : SB2);
#pragma unroll
        for (int kc = 0; kc < 8; ++kc) {
#pragma unroll
            for (int g2 = 0; g2 < 4; ++g2) {
                int row = g2 * 16 + brow;
                uint32_t ad = vb + row * 256 + (((kc * 2 + bch) ^ (row & 15)) << 4);
                uint32_t vh_[4], vl_[4];
                ldsm4(vh_, ad);
                ldsm4(vl_, ad + 16384);
                mma16816(o[2 * g2],     aPh[kc], vh_[0], vh_[1]);
                mma16816(o[2 * g2 + 1], aPh[kc], vh_[2], vh_[3]);
                mma16816(o[2 * g2],     aPh[kc], vl_[0], vl_[1]);
                mma16816(o[2 * g2 + 1], aPh[kc], vl_[2], vl_[3]);
                mma16816(o[2 * g2],     aPl[kc], vh_[0], vh_[1]);
                mma16816(o[2 * g2 + 1], aPl[kc], vh_[2], vh_[3]);
            }
        }
        __syncthreads();
    }

    // head-folded output
    {
        int qr = qbase + w * 16 + (lane >> 2);
        float* dp = outp + (size_t)qr * (DH * BH) + b * DH + (lane & 3) * 2;
#pragma unroll
        for (int g = 0; g < 8; ++g) {
            *(float2*)(dp + g * 8) = make_float2(o[g][0], o[g][1]);
            *(float2*)(dp + 8 * (DH * BH) + g * 8) = make_float2(o[g][2], o[g][3]);
        }
    }
}

extern "C" void kernel_launch(void* const* d_in, const int* in_sizes, int n_in,
                              void* d_out, int out_size) {
    const float* q = (const float*)d_in[0];
    const float* k = (const float*)d_in[1];
    const float* v = (const float*)d_in[2];

    float* outp = (float*)d_out;
    float* attn = outp + OUT_ELE;
    float* lattn = attn + ATT_ELE;

    cudaFuncSetAttribute(sdpa_fused, cudaFuncAttributeMaxDynamicSharedMemorySize, SMEM_TOT);

    prep_q<<<2048, 256>>>(q);
    prep_k<<<2048, 256>>>(k);
    prep_v<<<256, 256>>>(v);

    dim3 grid(LSEQ / 128, BH);
    sdpa_fused<<<grid, 256, SMEM_TOT>>>(attn, lattn, outp);
}